// round 9
// baseline (speedup 1.0000x reference)
#include <cuda_runtime.h>

// db4 wavedec level-4 (mode='symmetric'), one CTA per (b,c) row.
// R9: NT 256 -> 512. Smem/CTA is fixed by the row (66KB -> 3 CTAs/SM), so
// doubling threads/CTA doubles resident warps (24 -> 48/SM) and halves the
// serial depth of each level. Sliding-window chunks shrink to T={9,5,3,3}
// (all odd -> conflict-free LDS/STS as before).
//
// Output row layout (8218 f32): [cA4:518 | cD4:518 | cD3:1030 | cD2:2053 | cD1:4099]

#define L0    8192
#define O1    4099
#define O2    2053
#define O3    1030
#define O4    518
#define TOT   8218

#define NROWS 2048
#define NT    512

// SMEM layout (floats). Each buffer: [8-word left ext | body | right ext/pad].
#define CAP_A 8248          // level-1 worst tail read idx 8215; L3 reads < 2072
#define CAP_B 4152          // level-2 worst tail read idx 4117; L4 reads < 1046
#define CAP_S 4100          // cD scratch (max O1)
#define SMEM_FLOATS (CAP_A + CAP_B + CAP_S)   // 16500
#define SMEM_BYTES  (SMEM_FLOATS * 4)         // 66000

// pywt db4 rec_lo
#define R0  0.23037781330885523f
#define R1  0.7148465705525415f
#define R2  0.6308807679295904f
#define R3 (-0.02798376941698385f)
#define R4 (-0.18703481171888114f)
#define R5  0.030841381835986965f
#define R6  0.032883011666982945f
#define R7 (-0.010597401784997278f)

// Fill symmetric extension of a buffer whose body (length n) sits at b+8.
// Left:  b[2+m] = body[5-m]   (m=0..5)   -> in[-6..-1]
// Right: b[8+n+m] = body[n-1-m] (m=0..6) -> in[n..n+6]
static __device__ __forceinline__ void fill_ext(float* b, int n) {
    int t = threadIdx.x;
    if (t < 6) {
        b[2 + t] = b[8 + 5 - t];
    } else if (t < 13) {
        int m = t - 6;
        b[8 + n + m] = b[8 + n - 1 - m];
    }
}

// One DWT level with register sliding window.
// ext[8+j] = in[j]; thread t owns outputs [t*T, t*T+T). Requires ceil(n_out/T) <= NT.
// Window for output i is ext[2i+2 .. 2i+9] (even start -> aligned float2).
template<int T>
static __device__ __forceinline__ void dwt_level_reg(
    const float* __restrict__ ext, int n_out,
    float* __restrict__ outA, float* __restrict__ outD)
{
    const int i0 = threadIdx.x * T;
    if (i0 >= n_out) return;

    const int base = 2 * i0 + 2;
    float2 p0 = *reinterpret_cast<const float2*>(ext + base);
    float2 p1 = *reinterpret_cast<const float2*>(ext + base + 2);
    float2 p2 = *reinterpret_cast<const float2*>(ext + base + 4);
    float w0 = p0.x, w1 = p0.y, w2 = p1.x, w3 = p1.y, w4 = p2.x, w5 = p2.y;

    if (i0 + T <= n_out) {
        #pragma unroll
        for (int j = 0; j < T; j++) {
            float2 nv = *reinterpret_cast<const float2*>(ext + base + 6 + 2 * j);
            float w6 = nv.x, w7 = nv.y;
            float lo = R0 * w0;
            lo = fmaf(R1, w1, lo); lo = fmaf(R2, w2, lo); lo = fmaf(R3, w3, lo);
            lo = fmaf(R4, w4, lo); lo = fmaf(R5, w5, lo); lo = fmaf(R6, w6, lo);
            lo = fmaf(R7, w7, lo);
            float hi = R7 * w0;
            hi = fmaf(-R6, w1, hi); hi = fmaf( R5, w2, hi); hi = fmaf(-R4, w3, hi);
            hi = fmaf( R3, w4, hi); hi = fmaf(-R2, w5, hi); hi = fmaf( R1, w6, hi);
            hi = fmaf(-R0, w7, hi);
            outA[i0 + j] = lo;
            outD[i0 + j] = hi;
            w0 = w2; w1 = w3; w2 = w4; w3 = w5; w4 = w6; w5 = w7;
        }
    } else {
        #pragma unroll
        for (int j = 0; j < T; j++) {
            float2 nv = *reinterpret_cast<const float2*>(ext + base + 6 + 2 * j);
            float w6 = nv.x, w7 = nv.y;
            float lo = R0 * w0;
            lo = fmaf(R1, w1, lo); lo = fmaf(R2, w2, lo); lo = fmaf(R3, w3, lo);
            lo = fmaf(R4, w4, lo); lo = fmaf(R5, w5, lo); lo = fmaf(R6, w6, lo);
            lo = fmaf(R7, w7, lo);
            float hi = R7 * w0;
            hi = fmaf(-R6, w1, hi); hi = fmaf( R5, w2, hi); hi = fmaf(-R4, w3, hi);
            hi = fmaf( R3, w4, hi); hi = fmaf(-R2, w5, hi); hi = fmaf( R1, w6, hi);
            hi = fmaf(-R0, w7, hi);
            if (i0 + j < n_out) {
                outA[i0 + j] = lo;
                outD[i0 + j] = hi;
            }
            w0 = w2; w1 = w3; w2 = w4; w3 = w5; w4 = w6; w5 = w7;
        }
    }
}

__global__ void __launch_bounds__(NT)
wavedec_db4_l4_kernel(const float* __restrict__ x, float* __restrict__ out)
{
    extern __shared__ float sm[];
    float* A = sm;                   // ext buffer A, body at A+8
    float* B = sm + CAP_A;           // ext buffer B, body at B+8
    float* S = sm + CAP_A + CAP_B;   // cD staging scratch

    const int row = blockIdx.x;
    const float* xr = x + (size_t)row * L0;
    float* orow = out + (size_t)row * TOT;

    // Load row into A body (32B-aligned float4)
    {
        const float4* x4 = reinterpret_cast<const float4*>(xr);
        float4* a4 = reinterpret_cast<float4*>(A + 8);
        #pragma unroll 4
        for (int i = threadIdx.x; i < L0 / 4; i += NT) a4[i] = x4[i];
    }
    __syncthreads();
    fill_ext(A, L0);
    __syncthreads();

    // Level 1: 8192 -> 4099.  ceil(4099/9)=456 chunks <= 512.
    dwt_level_reg<9>(A, O1, B + 8, S);
    __syncthreads();
    fill_ext(B, O1);
    for (int i = threadIdx.x; i < O1; i += NT)
        orow[O4 + O4 + O3 + O2 + i] = S[i];          // cD1
    __syncthreads();

    // Level 2: 4099 -> 2053.  ceil(2053/5)=411 chunks.
    dwt_level_reg<5>(B, O2, A + 8, S);
    __syncthreads();
    fill_ext(A, O2);
    for (int i = threadIdx.x; i < O2; i += NT)
        orow[O4 + O4 + O3 + i] = S[i];               // cD2
    __syncthreads();

    // Level 3: 2053 -> 1030.  ceil(1030/3)=344 chunks.
    dwt_level_reg<3>(A, O3, B + 8, S);
    __syncthreads();
    fill_ext(B, O3);
    for (int i = threadIdx.x; i < O3; i += NT)
        orow[O4 + O4 + i] = S[i];                    // cD3
    __syncthreads();

    // Level 4: 1030 -> 518. Outputs straight to GMEM (tiny, scatter OK).
    dwt_level_reg<3>(B, O4, orow, orow + O4);        // cA4, cD4
}

extern "C" void kernel_launch(void* const* d_in, const int* in_sizes, int n_in,
                              void* d_out, int out_size)
{
    (void)in_sizes; (void)n_in; (void)out_size;
    const float* x = (const float*)d_in[0];
    float* out = (float*)d_out;

    cudaFuncSetAttribute(wavedec_db4_l4_kernel,
                         cudaFuncAttributeMaxDynamicSharedMemorySize, SMEM_BYTES);
    wavedec_db4_l4_kernel<<<NROWS, NT, SMEM_BYTES>>>(x, out);
}

// round 10
// speedup vs baseline: 1.0373x; 1.0373x over previous
#include <cuda_runtime.h>

// db4 wavedec level-4 (mode='symmetric'), one CTA per (b,c) row.
// R10: NT back to 256 (R9 showed 512 regressed). Packed-f32x2 polyphase
// filters: the float2 window loads ARE the polyphase pairs, so each filter is
// 4 x fma.rn.f32x2 (SASS FFMA2) + 1 horizontal add -> ~13 issued inst per
// output pair instead of ~20.
//
// Output row layout (8218 f32): [cA4:518 | cD4:518 | cD3:1030 | cD2:2053 | cD1:4099]

#define L0    8192
#define O1    4099
#define O2    2053
#define O3    1030
#define O4    518
#define TOT   8218

#define NROWS 2048
#define NT    256

// SMEM layout (floats). Each buffer: [8-word left ext | body | right ext/pad].
#define CAP_A 8248          // worst level-1 tail read idx 8235 < 8248
#define CAP_B 4152          // worst level-2 tail read idx 4127 < 4152
#define CAP_S 4100          // cD scratch (max O1)
#define SMEM_FLOATS (CAP_A + CAP_B + CAP_S)   // 16500
#define SMEM_BYTES  (SMEM_FLOATS * 4)         // 66000

// pywt db4 rec_lo
#define R0  0.23037781330885523f
#define R1  0.7148465705525415f
#define R2  0.6308807679295904f
#define R3 (-0.02798376941698385f)
#define R4 (-0.18703481171888114f)
#define R5  0.030841381835986965f
#define R6  0.032883011666982945f
#define R7 (-0.010597401784997278f)

typedef unsigned long long u64;

static __device__ __forceinline__ u64 pack2(float lo, float hi) {
    u64 r;
    asm("mov.b64 %0, {%1, %2};" : "=l"(r) : "f"(lo), "f"(hi));
    return r;
}
static __device__ __forceinline__ u64 mul2(u64 a, u64 b) {
    u64 d;
    asm("mul.rn.f32x2 %0, %1, %2;" : "=l"(d) : "l"(a), "l"(b));
    return d;
}
static __device__ __forceinline__ u64 fma2(u64 a, u64 b, u64 c) {
    u64 d;
    asm("fma.rn.f32x2 %0, %1, %2, %3;" : "=l"(d) : "l"(a), "l"(b), "l"(c));
    return d;
}
static __device__ __forceinline__ float hadd2(u64 v) {
    float x, y;
    asm("mov.b64 {%0, %1}, %2;" : "=f"(x), "=f"(y) : "l"(v));
    return x + y;
}

// Packed polyphase coefficients (built once per level call; pure asm -> CSE'd).
struct Coef {
    u64 cl0, cl1, cl2, cl3;   // lo filter: (R0,R1)(R2,R3)(R4,R5)(R6,R7)
    u64 ch0, ch1, ch2, ch3;   // hi filter: H_t = (-1)^t R_{7-t}
};
static __device__ __forceinline__ Coef make_coef() {
    Coef c;
    c.cl0 = pack2(R0, R1);  c.cl1 = pack2(R2, R3);
    c.cl2 = pack2(R4, R5);  c.cl3 = pack2(R6, R7);
    c.ch0 = pack2(R7, -R6); c.ch1 = pack2(R5, -R4);
    c.ch2 = pack2(R3, -R2); c.ch3 = pack2(R1, -R0);
    return c;
}

// Fill symmetric extension of a buffer whose body (length n) sits at b+8.
static __device__ __forceinline__ void fill_ext(float* b, int n) {
    int t = threadIdx.x;
    if (t < 6) {
        b[2 + t] = b[8 + 5 - t];
    } else if (t < 13) {
        int m = t - 6;
        b[8 + n + m] = b[8 + n - 1 - m];
    }
}

// One DWT level, register sliding window over polyphase pairs.
// p_k = (ext[2k], ext[2k+1]); output i uses p_{i+1}..p_{i+4}.
// Thread t owns outputs [t*T, t*T+T).  ceil(n_out/T) must be <= NT.
template<int T>
static __device__ __forceinline__ void dwt_level_reg(
    const float* __restrict__ ext, int n_out,
    float* __restrict__ outA, float* __restrict__ outD)
{
    const int i0 = threadIdx.x * T;
    if (i0 >= n_out) return;

    const Coef c = make_coef();
    const u64* pp = reinterpret_cast<const u64*>(ext) + (i0 + 1);

    u64 p1 = pp[0], p2 = pp[1], p3 = pp[2];

    if (i0 + T <= n_out) {
        #pragma unroll
        for (int j = 0; j < T; j++) {
            u64 p4 = pp[3 + j];
            u64 al = mul2(c.cl0, p1);
            al = fma2(c.cl1, p2, al);
            al = fma2(c.cl2, p3, al);
            al = fma2(c.cl3, p4, al);
            u64 ah = mul2(c.ch0, p1);
            ah = fma2(c.ch1, p2, ah);
            ah = fma2(c.ch2, p3, ah);
            ah = fma2(c.ch3, p4, ah);
            outA[i0 + j] = hadd2(al);
            outD[i0 + j] = hadd2(ah);
            p1 = p2; p2 = p3; p3 = p4;
        }
    } else {
        #pragma unroll
        for (int j = 0; j < T; j++) {
            u64 p4 = pp[3 + j];
            u64 al = mul2(c.cl0, p1);
            al = fma2(c.cl1, p2, al);
            al = fma2(c.cl2, p3, al);
            al = fma2(c.cl3, p4, al);
            u64 ah = mul2(c.ch0, p1);
            ah = fma2(c.ch1, p2, ah);
            ah = fma2(c.ch2, p3, ah);
            ah = fma2(c.ch3, p4, ah);
            if (i0 + j < n_out) {
                outA[i0 + j] = hadd2(al);
                outD[i0 + j] = hadd2(ah);
            }
            p1 = p2; p2 = p3; p3 = p4;
        }
    }
}

__global__ void __launch_bounds__(NT)
wavedec_db4_l4_kernel(const float* __restrict__ x, float* __restrict__ out)
{
    extern __shared__ float sm[];
    float* A = sm;                   // ext buffer A, body at A+8
    float* B = sm + CAP_A;           // ext buffer B, body at B+8 (CAP_A*4 % 8 == 0)
    float* S = sm + CAP_A + CAP_B;   // cD staging scratch

    const int row = blockIdx.x;
    const float* xr = x + (size_t)row * L0;
    float* orow = out + (size_t)row * TOT;

    // Load row into A body (32B-aligned float4)
    {
        const float4* x4 = reinterpret_cast<const float4*>(xr);
        float4* a4 = reinterpret_cast<float4*>(A + 8);
        #pragma unroll 4
        for (int i = threadIdx.x; i < L0 / 4; i += NT) a4[i] = x4[i];
    }
    __syncthreads();
    fill_ext(A, L0);
    __syncthreads();

    // Level 1: 8192 -> 4099.  ceil(4099/17)=242 chunks.
    dwt_level_reg<17>(A, O1, B + 8, S);
    __syncthreads();
    fill_ext(B, O1);
    for (int i = threadIdx.x; i < O1; i += NT)
        orow[O4 + O4 + O3 + O2 + i] = S[i];          // cD1
    __syncthreads();

    // Level 2: 4099 -> 2053.  ceil(2053/9)=229 chunks.
    dwt_level_reg<9>(B, O2, A + 8, S);
    __syncthreads();
    fill_ext(A, O2);
    for (int i = threadIdx.x; i < O2; i += NT)
        orow[O4 + O4 + O3 + i] = S[i];               // cD2
    __syncthreads();

    // Level 3: 2053 -> 1030.  ceil(1030/5)=206 chunks.
    dwt_level_reg<5>(A, O3, B + 8, S);
    __syncthreads();
    fill_ext(B, O3);
    for (int i = threadIdx.x; i < O3; i += NT)
        orow[O4 + O4 + i] = S[i];                    // cD3
    __syncthreads();

    // Level 4: 1030 -> 518. Outputs straight to GMEM (tiny, scatter OK).
    dwt_level_reg<3>(B, O4, orow, orow + O4);        // cA4, cD4
}

extern "C" void kernel_launch(void* const* d_in, const int* in_sizes, int n_in,
                              void* d_out, int out_size)
{
    (void)in_sizes; (void)n_in; (void)out_size;
    const float* x = (const float*)d_in[0];
    float* out = (float*)d_out;

    cudaFuncSetAttribute(wavedec_db4_l4_kernel,
                         cudaFuncAttributeMaxDynamicSharedMemorySize, SMEM_BYTES);
    wavedec_db4_l4_kernel<<<NROWS, NT, SMEM_BYTES>>>(x, out);
}